// round 16
// baseline (speedup 1.0000x reference)
#include <cuda_runtime.h>
#include <cuda_fp16.h>
#include <math.h>
#include <cstdint>

#define HD 2048
#define ID 1408
#define NE 8
#define NT 8192
#define NP (NT*2)

#define G1_BX 22   // ID/64 n-tiles (GEMM1)
#define G1_NC 64   // HD/32 k-chunks
#define G2_BX 16   // HD/128 n-tiles (GEMM2)
#define G2_NC 44   // ID/32 k-chunks

// ---- scratch (device globals) ----
__device__ int   g_cnt[NE];
__device__ int   g_list[NE * NP];
__device__ float g_pw[NP];
__device__ __align__(16) __half g_xh [(size_t)NT * HD];                    // 33 MB
__device__ __align__(16) __half g_act[(size_t)NP * ID];                    // 46 MB
__device__ __align__(16) __half g_w1h[(size_t)NE * G1_BX * G1_NC * 4096];  // 92 MB tiled
__device__ __align__(16) __half g_w2h[(size_t)NE * G2_BX * G2_NC * 4096];  // 46 MB tiled

// fp16 mma m16n8k16, fp32 accumulate
__device__ __forceinline__ void mma16(float* d, const uint32_t* a, uint32_t b0, uint32_t b1) {
    asm volatile("mma.sync.aligned.m16n8k16.row.col.f32.f16.f16.f32 "
        "{%0,%1,%2,%3}, {%4,%5,%6,%7}, {%8,%9}, {%0,%1,%2,%3};"
        : "+f"(d[0]), "+f"(d[1]), "+f"(d[2]), "+f"(d[3])
        : "r"(a[0]), "r"(a[1]), "r"(a[2]), "r"(a[3]), "r"(b0), "r"(b1));
}

__device__ __forceinline__ void ldsm4(uint32_t* r, uint32_t addr) {
    asm volatile("ldmatrix.sync.aligned.m8n8.x4.shared.b16 {%0,%1,%2,%3}, [%4];"
        : "=r"(r[0]), "=r"(r[1]), "=r"(r[2]), "=r"(r[3]) : "r"(addr));
}

__device__ __forceinline__ void cpa16(uint32_t saddr, const void* gp) {
    asm volatile("cp.async.cg.shared.global [%0], [%1], 16;"
                 :: "r"(saddr), "l"(__cvta_generic_to_global(gp)) : "memory");
}
#define CP_COMMIT() asm volatile("cp.async.commit_group;" ::: "memory")
#define CP_WAIT3()  asm volatile("cp.async.wait_group 3;" ::: "memory")

// SMEM: sp[64] @0 (pad 512); 5 stages of 12KB: A 4KB + B 8KB
#define SM_SP   0
#define STG_SZ  12288
#define SM_A(s) (512 + (s) * STG_SZ)
#define SM_B(s) (512 + (s) * STG_SZ + 4096)
#define SMEM_BYTES (512 + 5 * STG_SZ)
#define NSTG 5

// ============================================================
// prep_w1 / prep_w2: fp32 -> fp16, ldmatrix tile order
// ============================================================
__global__ __launch_bounds__(256) void prep_w1(const float* __restrict__ w1)
{
    int c = blockIdx.x, bx = blockIdx.y, e = blockIdx.z;
    if (c == 0 && bx == 0 && e == 0 && threadIdx.x < NE) g_cnt[threadIdx.x] = 0;
    const float* w1e = w1 + (size_t)e * 2 * ID * HD;
    __half* dst = g_w1h + (((size_t)e * G1_BX + bx) * G1_NC + c) * 4096;
    int tid = threadIdx.x;
#pragma unroll
    for (int s = 0; s < 2; s++) {
        int piece = tid * 2 + s;            // blk*32 + mat*8 + row
        int row = piece & 7;
        int mat = (piece >> 3) & 3;
        int blk = piece >> 5;               // ntp*2 + kt
        int kt = blk & 1, ntp = blk >> 1;
        int nt = ntp * 2 + (mat >> 1);
        int kh8 = mat & 1;
        int wrow = (nt & 1) * ID + bx * 64 + (nt >> 1) * 8 + row;
        int k = c * 32 + kt * 16 + kh8 * 8;
        const float* src = w1e + (size_t)wrow * HD + k;
        __half hv[8];
#pragma unroll
        for (int kk = 0; kk < 8; kk++) hv[kk] = __float2half_rn(src[kk]);
        *(uint4*)(dst + piece * 8) = *(uint4*)hv;
    }
}

__global__ __launch_bounds__(256) void prep_w2(const float* __restrict__ w2)
{
    int c = blockIdx.x, bx = blockIdx.y, e = blockIdx.z;
    const float* w2e = w2 + (size_t)e * HD * ID;
    __half* dst = g_w2h + (((size_t)e * G2_BX + bx) * G2_NC + c) * 4096;
    int tid = threadIdx.x;
#pragma unroll
    for (int s = 0; s < 2; s++) {
        int piece = tid * 2 + s;
        int row = piece & 7;
        int mat = (piece >> 3) & 3;
        int blk = piece >> 5;
        int kt = blk & 1, ntp = blk >> 1;
        int nt = ntp * 2 + (mat >> 1);
        int kh8 = mat & 1;
        int wrow = bx * 128 + nt * 8 + row;
        int k = c * 32 + kt * 16 + kh8 * 8;
        const float* src = w2e + (size_t)wrow * ID + k;
        __half hv[8];
#pragma unroll
        for (int kk = 0; kk < 8; kk++) hv[kk] = __float2half_rn(src[kk]);
        *(uint4*)(dst + piece * 8) = *(uint4*)hv;
    }
}

// ============================================================
// router: 4 tokens per warp — rw loads amortized 4x.
// ============================================================
__global__ __launch_bounds__(256) void router_kernel(
    const float* __restrict__ x, const float* __restrict__ rw)
{
    int tid = threadIdx.x;
    int warp = tid >> 5, lane = tid & 31;
    int t0 = (blockIdx.x * 8 + warp) * 4;

    const float4* rwv = reinterpret_cast<const float4*>(rw);
    const float4* xt[4];
    uint2* xh[4];
#pragma unroll
    for (int tk = 0; tk < 4; tk++) {
        xt[tk] = reinterpret_cast<const float4*>(x + (size_t)(t0 + tk) * HD);
        xh[tk] = reinterpret_cast<uint2*>(g_xh + (size_t)(t0 + tk) * HD);
    }

    float acc[4][NE];
#pragma unroll
    for (int tk = 0; tk < 4; tk++)
#pragma unroll
        for (int e = 0; e < NE; e++) acc[tk][e] = 0.f;

#pragma unroll 4
    for (int i = 0; i < 16; i++) {
        int idx = lane + i * 32;
        float4 wv[NE];
#pragma unroll
        for (int e = 0; e < NE; e++) wv[e] = __ldg(rwv + e * (HD/4) + idx);
#pragma unroll
        for (int tk = 0; tk < 4; tk++) {
            float4 xv = xt[tk][idx];
            __half2 h0 = __floats2half2_rn(xv.x, xv.y);
            __half2 h1 = __floats2half2_rn(xv.z, xv.w);
            uint2 o; o.x = *(uint32_t*)&h0; o.y = *(uint32_t*)&h1;
            xh[tk][idx] = o;
#pragma unroll
            for (int e = 0; e < NE; e++)
                acc[tk][e] += xv.x * wv[e].x + xv.y * wv[e].y + xv.z * wv[e].z + xv.w * wv[e].w;
        }
    }
#pragma unroll
    for (int off = 16; off; off >>= 1)
#pragma unroll
        for (int tk = 0; tk < 4; tk++)
#pragma unroll
            for (int e = 0; e < NE; e++)
                acc[tk][e] += __shfl_xor_sync(0xffffffffu, acc[tk][e], off);

    if (lane == 0) {
#pragma unroll
        for (int tk = 0; tk < 4; tk++) {
            int t = t0 + tk;
            int i0 = 0; float v0 = acc[tk][0];
#pragma unroll
            for (int e = 1; e < NE; e++) if (acc[tk][e] > v0) { v0 = acc[tk][e]; i0 = e; }
            int i1 = -1; float v1 = -1e30f;
#pragma unroll
            for (int e = 0; e < NE; e++) if (e != i0 && acc[tk][e] > v1) { v1 = acc[tk][e]; i1 = e; }
            float w0 = 1.f / (1.f + expf(v1 - v0));
            g_pw[2*t] = w0;  g_pw[2*t+1] = 1.f - w0;
            int pos0 = atomicAdd(&g_cnt[i0], 1);
            g_list[i0 * NP + pos0] = 2*t;
            int pos1 = atomicAdd(&g_cnt[i1], 1);
            g_list[i1 * NP + pos1] = 2*t+1;
        }
    }
}

// ============================================================
// GEMM1: 64M x 128Brows x K32 chunks, warp tile 32x32, 3 CTA/SM,
// 5-stage cp.async pipeline (3 outstanding groups)
// ============================================================
__global__ __launch_bounds__(256, 3) void gemm1_tc()
{
    const int e = blockIdx.z;
    const int cnt = g_cnt[e];
    const int m0 = blockIdx.y * 64;
    if (m0 >= cnt) return;
    const int bx = blockIdx.x;
    const int n0a = bx * 64;

    extern __shared__ char smem[];
    int* sp = (int*)(smem + SM_SP);
    const uint32_t sb = (uint32_t)__cvta_generic_to_shared(smem);

    const int tid = threadIdx.x;
    const int w = tid >> 5, lane = tid & 31;

    if (tid < 64) { int m = m0 + tid; sp[tid] = (m < cnt) ? g_list[e * NP + m] : -1; }
    __syncthreads();

    const int m_row = tid >> 2;
    const int pa = sp[m_row];
    const __half* asrc = g_xh + (size_t)(pa >= 0 ? (pa >> 1) : 0) * HD;
    const int amt = m_row >> 4, arow = m_row & 7, amh = (m_row >> 3) & 1;
    const int g8 = tid & 3;
    const int akt = g8 >> 1, akh8 = g8 & 1;
    const uint32_t dstA = (uint32_t)((amt * 2 + akt) * 512 + (amh + 2 * akh8) * 128 + arow * 16);
    const int srcA = g8 * 8;
    const __half* wsrc = g_w1h + (((size_t)e * G1_BX + bx) * G1_NC) * 4096;

    float acc[2][4][4];
#pragma unroll
    for (int i = 0; i < 2; i++)
#pragma unroll
        for (int n = 0; n < 4; n++)
#pragma unroll
            for (int c2 = 0; c2 < 4; c2++) acc[i][n][c2] = 0.f;

#pragma unroll
    for (int pc = 0; pc < 4; pc++) {
        uint32_t ab = sb + SM_A(pc), bb = sb + SM_B(pc);
        cpa16(ab + dstA, asrc + pc * 32 + srcA);
#pragma unroll
        for (int s = 0; s < 2; s++)
            cpa16(bb + tid * 32 + s * 16, wsrc + (size_t)pc * 4096 + tid * 16 + s * 8);
        CP_COMMIT();
    }

    const int wm = w >> 2;
    const int wn = w & 3;
    const uint32_t loff = (uint32_t)((lane >> 3) * 128 + (lane & 7) * 16);

    const int NC = G1_NC;
    for (int c = 0; c < NC; c++) {
        CP_WAIT3();
        __syncthreads();
        if (c + 4 < NC) {
            const int nc2 = c + 4;
            const int st2 = nc2 % NSTG;
            uint32_t ab2 = sb + SM_A(st2), bb2 = sb + SM_B(st2);
            cpa16(ab2 + dstA, asrc + nc2 * 32 + srcA);
#pragma unroll
            for (int s = 0; s < 2; s++)
                cpa16(bb2 + tid * 32 + s * 16, wsrc + (size_t)nc2 * 4096 + tid * 16 + s * 8);
        }
        CP_COMMIT();
        const int st = c % NSTG;
        const uint32_t ab = sb + SM_A(st), bb = sb + SM_B(st);
#pragma unroll
        for (int kt = 0; kt < 2; kt++) {
            uint32_t A0[4], A1[4];
            ldsm4(A0, ab + (uint32_t)(((wm * 2 + 0) * 2 + kt) * 512) + loff);
            ldsm4(A1, ab + (uint32_t)(((wm * 2 + 1) * 2 + kt) * 512) + loff);
#pragma unroll
            for (int j = 0; j < 2; j++) {
                uint32_t B[4];
                ldsm4(B, bb + (uint32_t)(((wn * 2 + j) * 2 + kt) * 512) + loff);
                mma16(acc[0][2*j],   A0, B[0], B[1]);
                mma16(acc[1][2*j],   A1, B[0], B[1]);
                mma16(acc[0][2*j+1], A0, B[2], B[3]);
                mma16(acc[1][2*j+1], A1, B[2], B[3]);
            }
        }
    }

    // epilogue: n8 even = gate, odd = up -> silu(gate)*up, fp16 out
    const int gid = lane >> 2, ctg = lane & 3;
#pragma unroll
    for (int i = 0; i < 2; i++) {
        int r0 = wm * 32 + i * 16 + gid;
        int p0 = sp[r0];
        int p1 = sp[r0 + 8];
#pragma unroll
        for (int j = 0; j < 2; j++) {
            float* g = acc[i][2 * j];
            float* u = acc[i][2 * j + 1];
            int col = n0a + (wn * 2 + j) * 8 + 2 * ctg;
            if (p0 >= 0) {
                float h0 = u[0] * g[0] / (1.f + __expf(-g[0]));
                float h1 = u[1] * g[1] / (1.f + __expf(-g[1]));
                *(__half2*)(g_act + (size_t)p0 * ID + col) = __floats2half2_rn(h0, h1);
            }
            if (p1 >= 0) {
                float h2 = u[2] * g[2] / (1.f + __expf(-g[2]));
                float h3 = u[3] * g[3] / (1.f + __expf(-g[3]));
                *(__half2*)(g_act + (size_t)p1 * ID + col) = __floats2half2_rn(h2, h3);
            }
        }
    }
}

// ============================================================
// GEMM2: 64M x 128N x K32 chunks, warp tile 32x32, 3 CTA/SM,
// 5-stage pipeline; fused combine via REDG atomics
// ============================================================
__global__ __launch_bounds__(256, 3) void gemm2_tc(float* __restrict__ out)
{
    const int e = blockIdx.z;
    const int cnt = g_cnt[e];
    const int m0 = blockIdx.y * 64;
    if (m0 >= cnt) return;
    const int bx = blockIdx.x;
    const int n0 = bx * 128;

    extern __shared__ char smem[];
    int* sp = (int*)(smem + SM_SP);
    const uint32_t sb = (uint32_t)__cvta_generic_to_shared(smem);

    const int tid = threadIdx.x;
    const int w = tid >> 5, lane = tid & 31;

    if (tid < 64) { int m = m0 + tid; sp[tid] = (m < cnt) ? g_list[e * NP + m] : -1; }
    __syncthreads();

    const int m_row = tid >> 2;
    const int pa = sp[m_row];
    const __half* asrc = g_act + (size_t)(pa >= 0 ? pa : 0) * ID;
    const int amt = m_row >> 4, arow = m_row & 7, amh = (m_row >> 3) & 1;
    const int g8 = tid & 3;
    const int akt = g8 >> 1, akh8 = g8 & 1;
    const uint32_t dstA = (uint32_t)((amt * 2 + akt) * 512 + (amh + 2 * akh8) * 128 + arow * 16);
    const int srcA = g8 * 8;
    const __half* wsrc = g_w2h + (((size_t)e * G2_BX + bx) * G2_NC) * 4096;

    float acc[2][4][4];
#pragma unroll
    for (int i = 0; i < 2; i++)
#pragma unroll
        for (int n = 0; n < 4; n++)
#pragma unroll
            for (int c2 = 0; c2 < 4; c2++) acc[i][n][c2] = 0.f;

#pragma unroll
    for (int pc = 0; pc < 4; pc++) {
        uint32_t ab = sb + SM_A(pc), bb = sb + SM_B(pc);
        cpa16(ab + dstA, asrc + pc * 32 + srcA);
#pragma unroll
        for (int s = 0; s < 2; s++)
            cpa16(bb + tid * 32 + s * 16, wsrc + (size_t)pc * 4096 + tid * 16 + s * 8);
        CP_COMMIT();
    }

    const int wm = w >> 2;
    const int wn = w & 3;
    const uint32_t loff = (uint32_t)((lane >> 3) * 128 + (lane & 7) * 16);

    const int NC = G2_NC;
    for (int c = 0; c < NC; c++) {
        CP_WAIT3();
        __syncthreads();
        if (c + 4 < NC) {
            const int nc2 = c + 4;
            const int st2 = nc2 % NSTG;
            uint32_t ab2 = sb + SM_A(st2), bb2 = sb + SM_B(st2);
            cpa16(ab2 + dstA, asrc + nc2 * 32 + srcA);
#pragma unroll
            for (int s = 0; s < 2; s++)
                cpa16(bb2 + tid * 32 + s * 16, wsrc + (size_t)nc2 * 4096 + tid * 16 + s * 8);
        }
        CP_COMMIT();
        const int st = c % NSTG;
        const uint32_t ab = sb + SM_A(st), bb = sb + SM_B(st);
#pragma unroll
        for (int kt = 0; kt < 2; kt++) {
            uint32_t A0[4], A1[4];
            ldsm4(A0, ab + (uint32_t)(((wm * 2 + 0) * 2 + kt) * 512) + loff);
            ldsm4(A1, ab + (uint32_t)(((wm * 2 + 1) * 2 + kt) * 512) + loff);
#pragma unroll
            for (int j = 0; j < 2; j++) {
                uint32_t B[4];
                ldsm4(B, bb + (uint32_t)(((wn * 2 + j) * 2 + kt) * 512) + loff);
                mma16(acc[0][2*j],   A0, B[0], B[1]);
                mma16(acc[1][2*j],   A1, B[0], B[1]);
                mma16(acc[0][2*j+1], A0, B[2], B[3]);
                mma16(acc[1][2*j+1], A1, B[2], B[3]);
            }
        }
    }

    // fused combine: out[p>>1] += pw[p] * acc
    const int gid = lane >> 2, ctg = lane & 3;
#pragma unroll
    for (int i = 0; i < 2; i++) {
        int r0 = wm * 32 + i * 16 + gid;
        int p0 = sp[r0];
        int p1 = sp[r0 + 8];
        float pw0 = (p0 >= 0) ? g_pw[p0] : 0.f;
        float pw1 = (p1 >= 0) ? g_pw[p1] : 0.f;
        float* d0 = out + (size_t)(p0 >= 0 ? (p0 >> 1) : 0) * HD;
        float* d1 = out + (size_t)(p1 >= 0 ? (p1 >> 1) : 0) * HD;
#pragma unroll
        for (int j = 0; j < 2; j++) {
#pragma unroll
            for (int b = 0; b < 2; b++) {
                int col = n0 + ((wn * 2 + j) * 2 + b) * 8 + 2 * ctg;
                float* a = acc[i][2 * j + b];
                if (p0 >= 0) {
                    atomicAdd(d0 + col,     pw0 * a[0]);
                    atomicAdd(d0 + col + 1, pw0 * a[1]);
                }
                if (p1 >= 0) {
                    atomicAdd(d1 + col,     pw1 * a[2]);
                    atomicAdd(d1 + col + 1, pw1 * a[3]);
                }
            }
        }
    }
}

// ============================================================
extern "C" void kernel_launch(void* const* d_in, const int* in_sizes, int n_in,
                              void* d_out, int out_size)
{
    const float* x  = (const float*)d_in[0];
    const float* rw = (const float*)d_in[1];
    const float* w1 = (const float*)d_in[2];
    const float* w2 = (const float*)d_in[3];
    float* out = (float*)d_out;

    cudaFuncSetAttribute(gemm1_tc, cudaFuncAttributeMaxDynamicSharedMemorySize, SMEM_BYTES);
    cudaFuncSetAttribute(gemm2_tc, cudaFuncAttributeMaxDynamicSharedMemorySize, SMEM_BYTES);

    cudaMemsetAsync(out, 0, (size_t)out_size * sizeof(float));
    prep_w1<<<dim3(G1_NC, G1_BX, NE), 256>>>(w1);   // also zeroes g_cnt
    prep_w2<<<dim3(G2_NC, G2_BX, NE), 256>>>(w2);
    router_kernel<<<NT/32, 256>>>(x, rw);           // 4 tokens/warp
    gemm1_tc<<<dim3(G1_BX, NP/64, NE), 256, SMEM_BYTES>>>();
    gemm2_tc<<<dim3(G2_BX, NP/64, NE), 256, SMEM_BYTES>>>(out);
}

// round 17
// speedup vs baseline: 1.0385x; 1.0385x over previous
#include <cuda_runtime.h>
#include <cuda_fp16.h>
#include <math.h>
#include <cstdint>

#define HD 2048
#define ID 1408
#define NE 8
#define NT 8192
#define NP (NT*2)

#define G1_BX 22   // ID/64 n-tiles (GEMM1)
#define G1_NC 64   // HD/32 k-chunks
#define G2_BX 16   // HD/128 n-tiles (GEMM2)
#define G2_NC 44   // ID/32 k-chunks

// ---- scratch (device globals) ----
__device__ int   g_cnt[NE];
__device__ int   g_list[NE * NP];
__device__ float g_pw[NP];
__device__ __align__(16) __half g_xh [(size_t)NT * HD];                    // 33 MB
__device__ __align__(16) __half g_act[(size_t)NP * ID];                    // 46 MB
__device__ __align__(16) __half g_w1h[(size_t)NE * G1_BX * G1_NC * 4096];  // 92 MB tiled
__device__ __align__(16) __half g_w2h[(size_t)NE * G2_BX * G2_NC * 4096];  // 46 MB tiled

// fp16 mma m16n8k16, fp32 accumulate
__device__ __forceinline__ void mma16(float* d, const uint32_t* a, uint32_t b0, uint32_t b1) {
    asm volatile("mma.sync.aligned.m16n8k16.row.col.f32.f16.f16.f32 "
        "{%0,%1,%2,%3}, {%4,%5,%6,%7}, {%8,%9}, {%0,%1,%2,%3};"
        : "+f"(d[0]), "+f"(d[1]), "+f"(d[2]), "+f"(d[3])
        : "r"(a[0]), "r"(a[1]), "r"(a[2]), "r"(a[3]), "r"(b0), "r"(b1));
}

__device__ __forceinline__ void ldsm4(uint32_t* r, uint32_t addr) {
    asm volatile("ldmatrix.sync.aligned.m8n8.x4.shared.b16 {%0,%1,%2,%3}, [%4];"
        : "=r"(r[0]), "=r"(r[1]), "=r"(r[2]), "=r"(r[3]) : "r"(addr));
}

__device__ __forceinline__ void cpa16(uint32_t saddr, const void* gp) {
    asm volatile("cp.async.cg.shared.global [%0], [%1], 16;"
                 :: "r"(saddr), "l"(__cvta_generic_to_global(gp)) : "memory");
}
#define CP_COMMIT() asm volatile("cp.async.commit_group;" ::: "memory")
#define CP_WAIT2()  asm volatile("cp.async.wait_group 2;" ::: "memory")

// SMEM: sp[64] @0 (pad 512); 4 stages of 12KB: A 4KB + B 8KB
#define SM_SP   0
#define STG_SZ  12288
#define SM_A(s) (512 + (s) * STG_SZ)
#define SM_B(s) (512 + (s) * STG_SZ + 4096)
#define SMEM_BYTES (512 + 4 * STG_SZ)
#define NSTG 4

// ============================================================
// prep_w1 / prep_w2: fp32 -> fp16, ldmatrix tile order
// ============================================================
__global__ __launch_bounds__(256) void prep_w1(const float* __restrict__ w1)
{
    int c = blockIdx.x, bx = blockIdx.y, e = blockIdx.z;
    if (c == 0 && bx == 0 && e == 0 && threadIdx.x < NE) g_cnt[threadIdx.x] = 0;
    const float* w1e = w1 + (size_t)e * 2 * ID * HD;
    __half* dst = g_w1h + (((size_t)e * G1_BX + bx) * G1_NC + c) * 4096;
    int tid = threadIdx.x;
#pragma unroll
    for (int s = 0; s < 2; s++) {
        int piece = tid * 2 + s;            // blk*32 + mat*8 + row
        int row = piece & 7;
        int mat = (piece >> 3) & 3;
        int blk = piece >> 5;               // ntp*2 + kt
        int kt = blk & 1, ntp = blk >> 1;
        int nt = ntp * 2 + (mat >> 1);
        int kh8 = mat & 1;
        int wrow = (nt & 1) * ID + bx * 64 + (nt >> 1) * 8 + row;
        int k = c * 32 + kt * 16 + kh8 * 8;
        const float* src = w1e + (size_t)wrow * HD + k;
        __half hv[8];
#pragma unroll
        for (int kk = 0; kk < 8; kk++) hv[kk] = __float2half_rn(src[kk]);
        *(uint4*)(dst + piece * 8) = *(uint4*)hv;
    }
}

__global__ __launch_bounds__(256) void prep_w2(const float* __restrict__ w2)
{
    int c = blockIdx.x, bx = blockIdx.y, e = blockIdx.z;
    const float* w2e = w2 + (size_t)e * HD * ID;
    __half* dst = g_w2h + (((size_t)e * G2_BX + bx) * G2_NC + c) * 4096;
    int tid = threadIdx.x;
#pragma unroll
    for (int s = 0; s < 2; s++) {
        int piece = tid * 2 + s;
        int row = piece & 7;
        int mat = (piece >> 3) & 3;
        int blk = piece >> 5;
        int kt = blk & 1, ntp = blk >> 1;
        int nt = ntp * 2 + (mat >> 1);
        int kh8 = mat & 1;
        int wrow = bx * 128 + nt * 8 + row;
        int k = c * 32 + kt * 16 + kh8 * 8;
        const float* src = w2e + (size_t)wrow * ID + k;
        __half hv[8];
#pragma unroll
        for (int kk = 0; kk < 8; kk++) hv[kk] = __float2half_rn(src[kk]);
        *(uint4*)(dst + piece * 8) = *(uint4*)hv;
    }
}

// ============================================================
// router: 4 tokens per warp — rw loads amortized 4x.
// logits + top-2 softmax + inline scatter + x->fp16
// ============================================================
__global__ __launch_bounds__(256) void router_kernel(
    const float* __restrict__ x, const float* __restrict__ rw)
{
    int tid = threadIdx.x;
    int warp = tid >> 5, lane = tid & 31;
    int t0 = (blockIdx.x * 8 + warp) * 4;

    const float4* rwv = reinterpret_cast<const float4*>(rw);
    const float4* xt[4];
    uint2* xh[4];
#pragma unroll
    for (int tk = 0; tk < 4; tk++) {
        xt[tk] = reinterpret_cast<const float4*>(x + (size_t)(t0 + tk) * HD);
        xh[tk] = reinterpret_cast<uint2*>(g_xh + (size_t)(t0 + tk) * HD);
    }

    float acc[4][NE];
#pragma unroll
    for (int tk = 0; tk < 4; tk++)
#pragma unroll
        for (int e = 0; e < NE; e++) acc[tk][e] = 0.f;

#pragma unroll 4
    for (int i = 0; i < 16; i++) {
        int idx = lane + i * 32;
        float4 wv[NE];
#pragma unroll
        for (int e = 0; e < NE; e++) wv[e] = __ldg(rwv + e * (HD/4) + idx);
#pragma unroll
        for (int tk = 0; tk < 4; tk++) {
            float4 xv = xt[tk][idx];
            __half2 h0 = __floats2half2_rn(xv.x, xv.y);
            __half2 h1 = __floats2half2_rn(xv.z, xv.w);
            uint2 o; o.x = *(uint32_t*)&h0; o.y = *(uint32_t*)&h1;
            xh[tk][idx] = o;
#pragma unroll
            for (int e = 0; e < NE; e++)
                acc[tk][e] += xv.x * wv[e].x + xv.y * wv[e].y + xv.z * wv[e].z + xv.w * wv[e].w;
        }
    }
#pragma unroll
    for (int off = 16; off; off >>= 1)
#pragma unroll
        for (int tk = 0; tk < 4; tk++)
#pragma unroll
            for (int e = 0; e < NE; e++)
                acc[tk][e] += __shfl_xor_sync(0xffffffffu, acc[tk][e], off);

    if (lane == 0) {
#pragma unroll
        for (int tk = 0; tk < 4; tk++) {
            int t = t0 + tk;
            int i0 = 0; float v0 = acc[tk][0];
#pragma unroll
            for (int e = 1; e < NE; e++) if (acc[tk][e] > v0) { v0 = acc[tk][e]; i0 = e; }
            int i1 = -1; float v1 = -1e30f;
#pragma unroll
            for (int e = 0; e < NE; e++) if (e != i0 && acc[tk][e] > v1) { v1 = acc[tk][e]; i1 = e; }
            float w0 = 1.f / (1.f + expf(v1 - v0));
            g_pw[2*t] = w0;  g_pw[2*t+1] = 1.f - w0;
            int pos0 = atomicAdd(&g_cnt[i0], 1);
            g_list[i0 * NP + pos0] = 2*t;
            int pos1 = atomicAdd(&g_cnt[i1], 1);
            g_list[i1 * NP + pos1] = 2*t+1;
        }
    }
}

// ============================================================
// GEMM1: 64M x 128Brows x K32 chunks, warp tile 32x32, 3 CTA/SM
// ============================================================
__global__ __launch_bounds__(256, 3) void gemm1_tc()
{
    const int e = blockIdx.z;
    const int cnt = g_cnt[e];
    const int m0 = blockIdx.y * 64;
    if (m0 >= cnt) return;
    const int bx = blockIdx.x;
    const int n0a = bx * 64;

    extern __shared__ char smem[];
    int* sp = (int*)(smem + SM_SP);
    const uint32_t sb = (uint32_t)__cvta_generic_to_shared(smem);

    const int tid = threadIdx.x;
    const int w = tid >> 5, lane = tid & 31;

    if (tid < 64) { int m = m0 + tid; sp[tid] = (m < cnt) ? g_list[e * NP + m] : -1; }
    __syncthreads();

    const int m_row = tid >> 2;
    const int pa = sp[m_row];
    const __half* asrc = g_xh + (size_t)(pa >= 0 ? (pa >> 1) : 0) * HD;
    const int amt = m_row >> 4, arow = m_row & 7, amh = (m_row >> 3) & 1;
    const int g8 = tid & 3;
    const int akt = g8 >> 1, akh8 = g8 & 1;
    const uint32_t dstA = (uint32_t)((amt * 2 + akt) * 512 + (amh + 2 * akh8) * 128 + arow * 16);
    const int srcA = g8 * 8;
    const __half* wsrc = g_w1h + (((size_t)e * G1_BX + bx) * G1_NC) * 4096;

    float acc[2][4][4];
#pragma unroll
    for (int i = 0; i < 2; i++)
#pragma unroll
        for (int n = 0; n < 4; n++)
#pragma unroll
            for (int c2 = 0; c2 < 4; c2++) acc[i][n][c2] = 0.f;

#pragma unroll
    for (int pc = 0; pc < 3; pc++) {
        uint32_t ab = sb + SM_A(pc), bb = sb + SM_B(pc);
        cpa16(ab + dstA, asrc + pc * 32 + srcA);
#pragma unroll
        for (int s = 0; s < 2; s++)
            cpa16(bb + tid * 32 + s * 16, wsrc + (size_t)pc * 4096 + tid * 16 + s * 8);
        CP_COMMIT();
    }

    const int wm = w >> 2;
    const int wn = w & 3;
    const uint32_t loff = (uint32_t)((lane >> 3) * 128 + (lane & 7) * 16);

    const int NC = G1_NC;
    for (int c = 0; c < NC; c++) {
        CP_WAIT2();
        __syncthreads();
        if (c + 3 < NC) {
            const int nc2 = c + 3;
            uint32_t ab2 = sb + SM_A(nc2 & (NSTG-1)), bb2 = sb + SM_B(nc2 & (NSTG-1));
            cpa16(ab2 + dstA, asrc + nc2 * 32 + srcA);
#pragma unroll
            for (int s = 0; s < 2; s++)
                cpa16(bb2 + tid * 32 + s * 16, wsrc + (size_t)nc2 * 4096 + tid * 16 + s * 8);
        }
        CP_COMMIT();
        const int st = c & (NSTG - 1);
        const uint32_t ab = sb + SM_A(st), bb = sb + SM_B(st);
#pragma unroll
        for (int kt = 0; kt < 2; kt++) {
            uint32_t A0[4], A1[4];
            ldsm4(A0, ab + (uint32_t)(((wm * 2 + 0) * 2 + kt) * 512) + loff);
            ldsm4(A1, ab + (uint32_t)(((wm * 2 + 1) * 2 + kt) * 512) + loff);
#pragma unroll
            for (int j = 0; j < 2; j++) {
                uint32_t B[4];
                ldsm4(B, bb + (uint32_t)(((wn * 2 + j) * 2 + kt) * 512) + loff);
                mma16(acc[0][2*j],   A0, B[0], B[1]);
                mma16(acc[1][2*j],   A1, B[0], B[1]);
                mma16(acc[0][2*j+1], A0, B[2], B[3]);
                mma16(acc[1][2*j+1], A1, B[2], B[3]);
            }
        }
    }

    // epilogue: n8 even = gate, odd = up -> silu(gate)*up, fp16 out
    const int gid = lane >> 2, ctg = lane & 3;
#pragma unroll
    for (int i = 0; i < 2; i++) {
        int r0 = wm * 32 + i * 16 + gid;
        int p0 = sp[r0];
        int p1 = sp[r0 + 8];
#pragma unroll
        for (int j = 0; j < 2; j++) {
            float* g = acc[i][2 * j];
            float* u = acc[i][2 * j + 1];
            int col = n0a + (wn * 2 + j) * 8 + 2 * ctg;
            if (p0 >= 0) {
                float h0 = u[0] * g[0] / (1.f + __expf(-g[0]));
                float h1 = u[1] * g[1] / (1.f + __expf(-g[1]));
                *(__half2*)(g_act + (size_t)p0 * ID + col) = __floats2half2_rn(h0, h1);
            }
            if (p1 >= 0) {
                float h2 = u[2] * g[2] / (1.f + __expf(-g[2]));
                float h3 = u[3] * g[3] / (1.f + __expf(-g[3]));
                *(__half2*)(g_act + (size_t)p1 * ID + col) = __floats2half2_rn(h2, h3);
            }
        }
    }
}

// ============================================================
// GEMM2: 64M x 128N x K32 chunks, warp tile 32x32, 3 CTA/SM
// fused combine via REDG atomics
// ============================================================
__global__ __launch_bounds__(256, 3) void gemm2_tc(float* __restrict__ out)
{
    const int e = blockIdx.z;
    const int cnt = g_cnt[e];
    const int m0 = blockIdx.y * 64;
    if (m0 >= cnt) return;
    const int bx = blockIdx.x;
    const int n0 = bx * 128;

    extern __shared__ char smem[];
    int* sp = (int*)(smem + SM_SP);
    const uint32_t sb = (uint32_t)__cvta_generic_to_shared(smem);

    const int tid = threadIdx.x;
    const int w = tid >> 5, lane = tid & 31;

    if (tid < 64) { int m = m0 + tid; sp[tid] = (m < cnt) ? g_list[e * NP + m] : -1; }
    __syncthreads();

    const int m_row = tid >> 2;
    const int pa = sp[m_row];
    const __half* asrc = g_act + (size_t)(pa >= 0 ? pa : 0) * ID;
    const int amt = m_row >> 4, arow = m_row & 7, amh = (m_row >> 3) & 1;
    const int g8 = tid & 3;
    const int akt = g8 >> 1, akh8 = g8 & 1;
    const uint32_t dstA = (uint32_t)((amt * 2 + akt) * 512 + (amh + 2 * akh8) * 128 + arow * 16);
    const int srcA = g8 * 8;
    const __half* wsrc = g_w2h + (((size_t)e * G2_BX + bx) * G2_NC) * 4096;

    float acc[2][4][4];
#pragma unroll
    for (int i = 0; i < 2; i++)
#pragma unroll
        for (int n = 0; n < 4; n++)
#pragma unroll
            for (int c2 = 0; c2 < 4; c2++) acc[i][n][c2] = 0.f;

#pragma unroll
    for (int pc = 0; pc < 3; pc++) {
        uint32_t ab = sb + SM_A(pc), bb = sb + SM_B(pc);
        cpa16(ab + dstA, asrc + pc * 32 + srcA);
#pragma unroll
        for (int s = 0; s < 2; s++)
            cpa16(bb + tid * 32 + s * 16, wsrc + (size_t)pc * 4096 + tid * 16 + s * 8);
        CP_COMMIT();
    }

    const int wm = w >> 2;
    const int wn = w & 3;
    const uint32_t loff = (uint32_t)((lane >> 3) * 128 + (lane & 7) * 16);

    const int NC = G2_NC;
    for (int c = 0; c < NC; c++) {
        CP_WAIT2();
        __syncthreads();
        if (c + 3 < NC) {
            const int nc2 = c + 3;
            uint32_t ab2 = sb + SM_A(nc2 & (NSTG-1)), bb2 = sb + SM_B(nc2 & (NSTG-1));
            cpa16(ab2 + dstA, asrc + nc2 * 32 + srcA);
#pragma unroll
            for (int s = 0; s < 2; s++)
                cpa16(bb2 + tid * 32 + s * 16, wsrc + (size_t)nc2 * 4096 + tid * 16 + s * 8);
        }
        CP_COMMIT();
        const int st = c & (NSTG - 1);
        const uint32_t ab = sb + SM_A(st), bb = sb + SM_B(st);
#pragma unroll
        for (int kt = 0; kt < 2; kt++) {
            uint32_t A0[4], A1[4];
            ldsm4(A0, ab + (uint32_t)(((wm * 2 + 0) * 2 + kt) * 512) + loff);
            ldsm4(A1, ab + (uint32_t)(((wm * 2 + 1) * 2 + kt) * 512) + loff);
#pragma unroll
            for (int j = 0; j < 2; j++) {
                uint32_t B[4];
                ldsm4(B, bb + (uint32_t)(((wn * 2 + j) * 2 + kt) * 512) + loff);
                mma16(acc[0][2*j],   A0, B[0], B[1]);
                mma16(acc[1][2*j],   A1, B[0], B[1]);
                mma16(acc[0][2*j+1], A0, B[2], B[3]);
                mma16(acc[1][2*j+1], A1, B[2], B[3]);
            }
        }
    }

    // fused combine: out[p>>1] += pw[p] * acc
    const int gid = lane >> 2, ctg = lane & 3;
#pragma unroll
    for (int i = 0; i < 2; i++) {
        int r0 = wm * 32 + i * 16 + gid;
        int p0 = sp[r0];
        int p1 = sp[r0 + 8];
        float pw0 = (p0 >= 0) ? g_pw[p0] : 0.f;
        float pw1 = (p1 >= 0) ? g_pw[p1] : 0.f;
        float* d0 = out + (size_t)(p0 >= 0 ? (p0 >> 1) : 0) * HD;
        float* d1 = out + (size_t)(p1 >= 0 ? (p1 >> 1) : 0) * HD;
#pragma unroll
        for (int j = 0; j < 2; j++) {
#pragma unroll
            for (int b = 0; b < 2; b++) {
                int col = n0 + ((wn * 2 + j) * 2 + b) * 8 + 2 * ctg;
                float* a = acc[i][2 * j + b];
                if (p0 >= 0) {
                    atomicAdd(d0 + col,     pw0 * a[0]);
                    atomicAdd(d0 + col + 1, pw0 * a[1]);
                }
                if (p1 >= 0) {
                    atomicAdd(d1 + col,     pw1 * a[2]);
                    atomicAdd(d1 + col + 1, pw1 * a[3]);
                }
            }
        }
    }
}

// ============================================================
extern "C" void kernel_launch(void* const* d_in, const int* in_sizes, int n_in,
                              void* d_out, int out_size)
{
    const float* x  = (const float*)d_in[0];
    const float* rw = (const float*)d_in[1];
    const float* w1 = (const float*)d_in[2];
    const float* w2 = (const float*)d_in[3];
    float* out = (float*)d_out;

    cudaFuncSetAttribute(gemm1_tc, cudaFuncAttributeMaxDynamicSharedMemorySize, SMEM_BYTES);
    cudaFuncSetAttribute(gemm2_tc, cudaFuncAttributeMaxDynamicSharedMemorySize, SMEM_BYTES);

    cudaMemsetAsync(out, 0, (size_t)out_size * sizeof(float));
    prep_w1<<<dim3(G1_NC, G1_BX, NE), 256>>>(w1);   // also zeroes g_cnt
    prep_w2<<<dim3(G2_NC, G2_BX, NE), 256>>>(w2);
    router_kernel<<<NT/32, 256>>>(x, rw);           // 4 tokens/warp
    gemm1_tc<<<dim3(G1_BX, NP/64, NE), 256, SMEM_BYTES>>>();
    gemm2_tc<<<dim3(G2_BX, NP/64, NE), 256, SMEM_BYTES>>>(out);
}